// round 1
// baseline (speedup 1.0000x reference)
#include <cuda_runtime.h>
#include <cuda_bf16.h>

// Problem constants
#define NB    32768
#define N_RX  8
#define N_TX  4
#define N_SYM 4

// SYMS = {-3,-1,1,3}/sqrt(5)
#define S_M3 (-1.3416407864998738f)
#define S_M1 (-0.44721359549995793f)
#define S_P1 ( 0.44721359549995793f)
#define S_P3 ( 1.3416407864998738f)

__device__ __forceinline__ float symval(int i) {
    // i is compile-time in all uses after unrolling, OR handled via selects below
    float ab = (i & 1) ? S_M1 : S_M3;
    float cd = (i & 1) ? S_P3 : S_P1;
    return (i & 2) ? cd : ab;
}

// select one of 4 register values by runtime index (no local memory)
__device__ __forceinline__ float qsel(float a, float b, float c, float d, int i) {
    float ab = (i & 1) ? b : a;
    float cd = (i & 1) ? d : c;
    return (i & 2) ? cd : ab;
}

__device__ __forceinline__ float laplace_log_cdf(float x) {
    // x < 0:  x - ln(2)
    // x >= 0: log1p(-0.5*exp(-x))  (argument of log in [0.5, 1])
    float e   = __expf(-fabsf(x));
    float pos = __logf(fmaf(-0.5f, e, 1.0f));
    return (x < 0.0f) ? (x - 0.69314718055994531f) : pos;
}

__global__ __launch_bounds__(256, 8)
void mfnet_layer_kernel(const float* __restrict__ log_qi_in,
                        const float* __restrict__ G,
                        const float* __restrict__ sqrt_2rho,
                        const float* __restrict__ alpha_ptr,
                        float* __restrict__ out)
{
    const int gtid = blockIdx.x * blockDim.x + threadIdx.x;
    const int b    = gtid >> 5;          // one warp per batch item
    const int lane = gtid & 31;
    if (b >= NB) return;

    const float alpha = __ldg(alpha_ptr);
    const float rho   = __ldg(&sqrt_2rho[b]);

    // k = i0*64 + i1*16 + i2*4 + i3 ; k = lane*8 + j
    // i0 = lane>>3, i1 = (lane>>1)&3, i2 = ((lane&1)<<1)|(j>>2), i3 = j&3
    const int i0 = lane >> 3;
    const int i1 = (lane >> 1) & 3;
    const int lb = lane & 1;

    const float s0 = qsel(S_M3, S_M1, S_P1, S_P3, i0);
    const float s1 = qsel(S_M3, S_M1, S_P1, S_P3, i1);

    // Per-r partials: base = rho*(g0*s0 + g1*s1), c2 = rho*g2, c3 = rho*g3
    float base[N_RX], c2[N_RX], c3[N_RX];
    const float4* Gv = reinterpret_cast<const float4*>(G) + (size_t)b * N_RX;
    #pragma unroll
    for (int r = 0; r < N_RX; r++) {
        float4 g = Gv[r];
        base[r] = rho * fmaf(g.x, s0, g.y * s1);
        c2[r]   = rho * g.z;
        c3[r]   = rho * g.w;
    }

    // log_p for this lane's 8 k-values
    float logp[8];
    #pragma unroll
    for (int j = 0; j < 8; j++) {
        const int jc = j >> 2;            // compile-time after unroll
        const int i3 = j & 3;             // compile-time after unroll
        // i2 = lb*2 + jc -> symbol select between two compile-time symbols by lb
        const float si2 = lb ? symval(2 | jc) : symval(jc);
        const float si3 = symval(i3);
        float acc = 0.0f;
        #pragma unroll
        for (int r = 0; r < N_RX; r++) {
            float x = fmaf(c3[r], si3, fmaf(c2[r], si2, base[r]));
            acc += laplace_log_cdf(x);
        }
        logp[j] = acc;
    }

    // Load log_qi [4][4]
    float lq[N_TX][N_SYM];
    const float4* Lv = reinterpret_cast<const float4*>(log_qi_in) + (size_t)b * N_TX;
    #pragma unroll
    for (int t = 0; t < N_TX; t++) {
        float4 v = Lv[t];
        lq[t][0] = v.x; lq[t][1] = v.y; lq[t][2] = v.z; lq[t][3] = v.w;
    }

    // Softmax per row
    float qi[N_TX][N_SYM];
    #pragma unroll
    for (int t = 0; t < N_TX; t++) {
        float e0 = __expf(lq[t][0]), e1 = __expf(lq[t][1]);
        float e2 = __expf(lq[t][2]), e3 = __expf(lq[t][3]);
        float inv = __frcp_rn(((e0 + e1) + (e2 + e3)));
        qi[t][0] = e0 * inv; qi[t][1] = e1 * inv;
        qi[t][2] = e2 * inv; qi[t][3] = e3 * inv;
    }

    // Hoisted per-lane qi factors
    float f0   = qsel(qi[0][0], qi[0][1], qi[0][2], qi[0][3], i0);
    float f1   = qsel(qi[1][0], qi[1][1], qi[1][2], qi[1][3], i1);
    float f2_0 = lb ? qi[2][2] : qi[2][0];   // i2 with jc=0
    float f2_1 = lb ? qi[2][3] : qi[2][1];   // i2 with jc=1

    #pragma unroll
    for (int xi = 0; xi < N_TX; xi++) {
        float acc[4] = {0.0f, 0.0f, 0.0f, 0.0f};

        #pragma unroll
        for (int j = 0; j < 8; j++) {
            const int jc = j >> 2;
            const int i3 = j & 3;
            const float f2 = jc ? f2_1 : f2_0;
            const float f3 = qi[3][i3];       // static index after unroll
            float w;
            int s;
            if (xi == 0)      { w = f1 * f2 * f3; s = i0; }
            else if (xi == 1) { w = f0 * f2 * f3; s = i1; }
            else if (xi == 2) { w = f0 * f1 * f3; s = (lb << 1) | jc; }
            else              { w = f0 * f1 * f2; s = i3; }
            const float v = w * logp[j];
            #pragma unroll
            for (int ss = 0; ss < 4; ss++)
                acc[ss] += (s == ss) ? v : 0.0f;
        }

        // Full warp butterfly reduce each bucket -> all lanes get totals
        #pragma unroll
        for (int ss = 0; ss < 4; ss++) {
            float a = acc[ss];
            a += __shfl_xor_sync(0xffffffffu, a, 16);
            a += __shfl_xor_sync(0xffffffffu, a, 8);
            a += __shfl_xor_sync(0xffffffffu, a, 4);
            a += __shfl_xor_sync(0xffffffffu, a, 2);
            a += __shfl_xor_sync(0xffffffffu, a, 1);
            acc[ss] = a;
        }

        // new_row = (1-alpha)*old + alpha*ex
        #pragma unroll
        for (int ss = 0; ss < 4; ss++)
            lq[xi][ss] = fmaf(1.0f - alpha, lq[xi][ss], alpha * acc[ss]);

        // Subtract row-max from every row (exactly as reference does each iter)
        #pragma unroll
        for (int t = 0; t < N_TX; t++) {
            float m = fmaxf(fmaxf(lq[t][0], lq[t][1]), fmaxf(lq[t][2], lq[t][3]));
            lq[t][0] -= m; lq[t][1] -= m; lq[t][2] -= m; lq[t][3] -= m;
        }

        // Recompute softmax of the just-updated row (needed by later iters)
        if (xi < 3) {
            float e0 = __expf(lq[xi][0]), e1 = __expf(lq[xi][1]);
            float e2 = __expf(lq[xi][2]), e3 = __expf(lq[xi][3]);
            float inv = __frcp_rn(((e0 + e1) + (e2 + e3)));
            qi[xi][0] = e0 * inv; qi[xi][1] = e1 * inv;
            qi[xi][2] = e2 * inv; qi[xi][3] = e3 * inv;
            if (xi == 0) f0 = qsel(qi[0][0], qi[0][1], qi[0][2], qi[0][3], i0);
            if (xi == 1) f1 = qsel(qi[1][0], qi[1][1], qi[1][2], qi[1][3], i1);
            if (xi == 2) {
                f2_0 = lb ? qi[2][2] : qi[2][0];
                f2_1 = lb ? qi[2][3] : qi[2][1];
            }
        }
    }

    // Write out: lanes 0..3 each write one row as float4
    if (lane < N_TX) {
        float4 o = make_float4(lq[lane][0], lq[lane][1], lq[lane][2], lq[lane][3]);
        reinterpret_cast<float4*>(out)[(size_t)b * N_TX + lane] = o;
    }
}

extern "C" void kernel_launch(void* const* d_in, const int* in_sizes, int n_in,
                              void* d_out, int out_size)
{
    const float* log_qi    = (const float*)d_in[0]; // (N,4,4)
    const float* G         = (const float*)d_in[1]; // (N,8,4)
    const float* sqrt_2rho = (const float*)d_in[2]; // (N,)
    // d_in[3] = n_var, unused by reference
    const float* alpha     = (const float*)d_in[4]; // scalar

    float* out = (float*)d_out;

    const int threads = 256;                 // 8 warps/block, 8 items/block
    const int blocks  = (NB * 32) / threads; // 4096
    mfnet_layer_kernel<<<blocks, threads>>>(log_qi, G, sqrt_2rho, alpha, out);
}

// round 2
// speedup vs baseline: 1.5245x; 1.5245x over previous
#include <cuda_runtime.h>

#define NB    32768
#define N_RX  8

// SYMS = {-3,-1,1,3}/sqrt(5)
#define S_M3 (-1.3416407864998738f)
#define S_M1 (-0.44721359549995793f)
#define S_P1 ( 0.44721359549995793f)
#define S_P3 ( 1.3416407864998738f)
#define LOG2E 1.4426950408889634f
#define LN2   0.6931471805599453f

__device__ __forceinline__ float symval(int i) {
    float ab = (i & 1) ? S_M1 : S_M3;
    float cd = (i & 1) ? S_P3 : S_P1;
    return (i & 2) ? cd : ab;
}
// select one of 4 register values by 2-bit index (no local memory)
__device__ __forceinline__ float qsel(float a, float b, float c, float d, int i) {
    float ab = (i & 1) ? b : a;
    float cd = (i & 1) ? d : c;
    return (i & 2) ? cd : ab;
}
__device__ __forceinline__ float rowmax4(const float* v) {
    return fmaxf(fmaxf(v[0], v[1]), fmaxf(v[2], v[3]));
}

__global__ __launch_bounds__(256, 4)
void mfnet_layer_kernel(const float* __restrict__ log_qi_in,
                        const float* __restrict__ G,
                        const float* __restrict__ sqrt_2rho,
                        const float* __restrict__ alpha_ptr,
                        float* __restrict__ out)
{
    const int gtid = blockIdx.x * blockDim.x + threadIdx.x;
    const int b    = gtid >> 5;          // one warp per batch item
    const int lane = gtid & 31;
    if (b >= NB) return;

    const float alpha = __ldg(alpha_ptr);
    const float rho2  = __ldg(&sqrt_2rho[b]) * LOG2E;  // fold log2e: work in log2 units

    // k = i0*64 + i1*16 + i2*4 + i3 ; k = lane*8 + j
    // i0 = lane>>3, i1 = (lane>>1)&3, i2 = ((lane&1)<<1)|(j>>2), i3 = j&3
    const int i0 = lane >> 3;
    const int i1 = (lane >> 1) & 3;
    const int lb = lane & 1;

    const float s0    = qsel(S_M3, S_M1, S_P1, S_P3, i0);
    const float s1    = qsel(S_M3, S_M1, S_P1, S_P3, i1);
    const float si2_0 = lb ? S_P1 : S_M3;   // symval(2lb + 0)
    const float si2_1 = lb ? S_P3 : S_M1;   // symval(2lb + 1)

    // Per-r partials in log2 units: t2[r][jc] = rho2*(g0 s0 + g1 s1 + g2 si2_jc), c3 = rho2*g3
    float t2[N_RX][2], c3[N_RX];
    const float4* Gv = reinterpret_cast<const float4*>(G) + (size_t)b * N_RX;
    #pragma unroll
    for (int r = 0; r < N_RX; r++) {
        float4 g   = Gv[r];
        float base = rho2 * fmaf(g.x, s0, g.y * s1);
        float c2   = rho2 * g.z;
        c3[r]      = rho2 * g.w;
        t2[r][0]   = fmaf(c2, si2_0, base);
        t2[r][1]   = fmaf(c2, si2_1, base);
    }

    // log_p (in log2 units) for this lane's 8 k-values.
    // logcdf2(x2) = min(x2,0) + log2(1 - 0.5*2^{-max(x2,0)})  [branchless; exact 0.5 factor at x<0]
    // Single LG2 per j: sum the mins, take log2 of the product of h's (h in [0.5,1) -> no underflow).
    float lp2[8];
    #pragma unroll
    for (int j = 0; j < 8; j++) {
        const int   jc  = j >> 2;
        const float si3 = symval(j & 3);
        float accm = 0.0f, prod = 1.0f;
        #pragma unroll
        for (int r = 0; r < N_RX; r++) {
            float x  = fmaf(c3[r], si3, t2[r][jc]);
            float mn = fminf(x, 0.0f);
            accm += mn;
            float e  = exp2f(mn - x);            // = 2^{-max(x,0)}, bare EX2
            prod *= fmaf(-0.5f, e, 1.0f);
        }
        lp2[j] = accm + __log2f(prod);
    }

    // Load log_qi [4][4]; stored values are never shifted, per-row offset tracked lazily.
    float lq[4][4], off[4];
    const float4* Lv = reinterpret_cast<const float4*>(log_qi_in) + (size_t)b * 4;
    #pragma unroll
    for (int t = 0; t < 4; t++) {
        float4 v = Lv[t];
        lq[t][0] = v.x; lq[t][1] = v.y; lq[t][2] = v.z; lq[t][3] = v.w;
    }
    off[0] = 0.0f;                // row 0's first update uses the raw row (reference order)
    off[1] = rowmax4(lq[1]);      // rows 1..3 see the iter-0 shift before their update
    off[2] = rowmax4(lq[2]);
    off[3] = rowmax4(lq[3]);

    // Initial softmax pieces (softmax is shift-invariant; iter-0 uses raw rows like reference)
    float f0, f1, f2_0, f2_1, qi3[4];
    {
        float e0 = __expf(lq[0][0]), e1 = __expf(lq[0][1]), e2 = __expf(lq[0][2]), e3 = __expf(lq[0][3]);
        f0 = qsel(e0, e1, e2, e3, i0) * __fdividef(1.0f, (e0 + e1) + (e2 + e3));
    }
    {
        float e0 = __expf(lq[1][0]), e1 = __expf(lq[1][1]), e2 = __expf(lq[1][2]), e3 = __expf(lq[1][3]);
        f1 = qsel(e0, e1, e2, e3, i1) * __fdividef(1.0f, (e0 + e1) + (e2 + e3));
    }
    {
        float e0 = __expf(lq[2][0]), e1 = __expf(lq[2][1]), e2 = __expf(lq[2][2]), e3 = __expf(lq[2][3]);
        float inv = __fdividef(1.0f, (e0 + e1) + (e2 + e3));
        f2_0 = (lb ? e2 : e0) * inv;
        f2_1 = (lb ? e3 : e1) * inv;
    }
    {
        float e0 = __expf(lq[3][0]), e1 = __expf(lq[3][1]), e2 = __expf(lq[3][2]), e3 = __expf(lq[3][3]);
        float inv = __fdividef(1.0f, (e0 + e1) + (e2 + e3));
        qi3[0] = e0 * inv; qi3[1] = e1 * inv; qi3[2] = e2 * inv; qi3[3] = e3 * inv;
    }

    // Shared partial sums: ul0/ul1 valid for xi=0,1 (via sum_wl) and xi=2 (rows 2,3 unchanged until then)
    float ul0 = fmaf(qi3[3], lp2[3], fmaf(qi3[2], lp2[2], fmaf(qi3[1], lp2[1], qi3[0] * lp2[0])));
    float ul1 = fmaf(qi3[3], lp2[7], fmaf(qi3[2], lp2[6], fmaf(qi3[1], lp2[5], qi3[0] * lp2[4])));
    float sum_wl = fmaf(f2_1, ul1, f2_0 * ul0);

    const float ap  = alpha * LN2;     // acc is in log2 units -> fold ln2 into alpha
    const float oma = 1.0f - alpha;
    const unsigned FULL = 0xffffffffu;

    // ---- xi = 0 : bucket s = i0 = lane>>3 (bits 3,4). Reduce over bits 0,1,2. ----
    {
        float a = f1 * sum_wl;
        a += __shfl_xor_sync(FULL, a, 1);
        a += __shfl_xor_sync(FULL, a, 2);
        a += __shfl_xor_sync(FULL, a, 4);
        float a0 = __shfl_sync(FULL, a, 0);
        float a1 = __shfl_sync(FULL, a, 8);
        float a2 = __shfl_sync(FULL, a, 16);
        float a3 = __shfl_sync(FULL, a, 24);
        float o = off[0];
        lq[0][0] = fmaf(oma, lq[0][0] - o, ap * a0);
        lq[0][1] = fmaf(oma, lq[0][1] - o, ap * a1);
        lq[0][2] = fmaf(oma, lq[0][2] - o, ap * a2);
        lq[0][3] = fmaf(oma, lq[0][3] - o, ap * a3);
        off[0] = rowmax4(lq[0]);
        float e0 = __expf(lq[0][0] - off[0]), e1 = __expf(lq[0][1] - off[0]);
        float e2 = __expf(lq[0][2] - off[0]), e3 = __expf(lq[0][3] - off[0]);
        f0 = qsel(e0, e1, e2, e3, i0) * __fdividef(1.0f, (e0 + e1) + (e2 + e3));
    }

    // ---- xi = 1 : bucket s = i1 = (lane>>1)&3 (bits 1,2). Reduce over bits 0,3,4. ----
    {
        float a = f0 * sum_wl;
        a += __shfl_xor_sync(FULL, a, 1);
        a += __shfl_xor_sync(FULL, a, 8);
        a += __shfl_xor_sync(FULL, a, 16);
        float a0 = __shfl_sync(FULL, a, 0);
        float a1 = __shfl_sync(FULL, a, 2);
        float a2 = __shfl_sync(FULL, a, 4);
        float a3 = __shfl_sync(FULL, a, 6);
        float o = off[1];
        lq[1][0] = fmaf(oma, lq[1][0] - o, ap * a0);
        lq[1][1] = fmaf(oma, lq[1][1] - o, ap * a1);
        lq[1][2] = fmaf(oma, lq[1][2] - o, ap * a2);
        lq[1][3] = fmaf(oma, lq[1][3] - o, ap * a3);
        off[1] = rowmax4(lq[1]);
        float e0 = __expf(lq[1][0] - off[1]), e1 = __expf(lq[1][1] - off[1]);
        float e2 = __expf(lq[1][2] - off[1]), e3 = __expf(lq[1][3] - off[1]);
        f1 = qsel(e0, e1, e2, e3, i1) * __fdividef(1.0f, (e0 + e1) + (e2 + e3));
    }

    // ---- xi = 2 : bucket s = i2 = 2*lb + jc. Two accs per lane; reduce over bits 1,2,3,4. ----
    float g0, g1;   // f01 * new qi2 selects, for xi=3
    {
        float f01 = f0 * f1;
        float a0 = f01 * ul0;   // jc=0 -> bucket 2*lb
        float a1 = f01 * ul1;   // jc=1 -> bucket 2*lb+1
        a0 += __shfl_xor_sync(FULL, a0, 2);  a1 += __shfl_xor_sync(FULL, a1, 2);
        a0 += __shfl_xor_sync(FULL, a0, 4);  a1 += __shfl_xor_sync(FULL, a1, 4);
        a0 += __shfl_xor_sync(FULL, a0, 8);  a1 += __shfl_xor_sync(FULL, a1, 8);
        a0 += __shfl_xor_sync(FULL, a0, 16); a1 += __shfl_xor_sync(FULL, a1, 16);
        float b0 = __shfl_sync(FULL, a0, 0);  // bucket 0 (even lanes, jc=0)
        float b1 = __shfl_sync(FULL, a1, 0);  // bucket 1
        float b2 = __shfl_sync(FULL, a0, 1);  // bucket 2 (odd lanes, jc=0)
        float b3 = __shfl_sync(FULL, a1, 1);  // bucket 3
        float o = off[2];
        lq[2][0] = fmaf(oma, lq[2][0] - o, ap * b0);
        lq[2][1] = fmaf(oma, lq[2][1] - o, ap * b1);
        lq[2][2] = fmaf(oma, lq[2][2] - o, ap * b2);
        lq[2][3] = fmaf(oma, lq[2][3] - o, ap * b3);
        off[2] = rowmax4(lq[2]);
        float e0 = __expf(lq[2][0] - off[2]), e1 = __expf(lq[2][1] - off[2]);
        float e2 = __expf(lq[2][2] - off[2]), e3 = __expf(lq[2][3] - off[2]);
        float inv = __fdividef(1.0f, (e0 + e1) + (e2 + e3));
        g0 = f01 * ((lb ? e2 : e0) * inv);
        g1 = f01 * ((lb ? e3 : e1) * inv);
    }

    // ---- xi = 3 : bucket s = i3 = j&3. Per-lane 4 values; full butterfly. ----
    {
        float v0 = fmaf(g1, lp2[4], g0 * lp2[0]);
        float v1 = fmaf(g1, lp2[5], g0 * lp2[1]);
        float v2 = fmaf(g1, lp2[6], g0 * lp2[2]);
        float v3 = fmaf(g1, lp2[7], g0 * lp2[3]);
        #pragma unroll
        for (int st = 1; st <= 16; st <<= 1) {
            v0 += __shfl_xor_sync(FULL, v0, st);
            v1 += __shfl_xor_sync(FULL, v1, st);
            v2 += __shfl_xor_sync(FULL, v2, st);
            v3 += __shfl_xor_sync(FULL, v3, st);
        }
        float o = off[3];
        lq[3][0] = fmaf(oma, lq[3][0] - o, ap * v0);
        lq[3][1] = fmaf(oma, lq[3][1] - o, ap * v1);
        lq[3][2] = fmaf(oma, lq[3][2] - o, ap * v2);
        lq[3][3] = fmaf(oma, lq[3][3] - o, ap * v3);
        off[3] = rowmax4(lq[3]);
    }

    // Output: actual values = stored - off (off[t] == rowmax(stored[t]) for all t now).
    // Lanes 0..3 write rows 0..3 as float4; select row registers by lane index.
    float r0 = qsel(lq[0][0] - off[0], lq[1][0] - off[1], lq[2][0] - off[2], lq[3][0] - off[3], lane);
    float r1 = qsel(lq[0][1] - off[0], lq[1][1] - off[1], lq[2][1] - off[2], lq[3][1] - off[3], lane);
    float r2 = qsel(lq[0][2] - off[0], lq[1][2] - off[1], lq[2][2] - off[2], lq[3][2] - off[3], lane);
    float r3 = qsel(lq[0][3] - off[0], lq[1][3] - off[1], lq[2][3] - off[2], lq[3][3] - off[3], lane);
    if (lane < 4) {
        reinterpret_cast<float4*>(out)[(size_t)b * 4 + lane] = make_float4(r0, r1, r2, r3);
    }
}

extern "C" void kernel_launch(void* const* d_in, const int* in_sizes, int n_in,
                              void* d_out, int out_size)
{
    const float* log_qi    = (const float*)d_in[0]; // (N,4,4)
    const float* G         = (const float*)d_in[1]; // (N,8,4)
    const float* sqrt_2rho = (const float*)d_in[2]; // (N,)
    // d_in[3] = n_var, unused by reference
    const float* alpha     = (const float*)d_in[4]; // scalar

    float* out = (float*)d_out;

    const int threads = 256;                 // 8 warps/block
    const int blocks  = (NB * 32) / threads; // 4096
    mfnet_layer_kernel<<<blocks, threads>>>(log_qi, G, sqrt_2rho, alpha, out);
}

// round 3
// speedup vs baseline: 1.9868x; 1.3033x over previous
#include <cuda_runtime.h>

#define NB    32768
#define N_RX  8

// SYMS = {-3,-1,1,3}/sqrt(5)
#define S_M3 (-1.3416407864998738f)
#define S_M1 (-0.44721359549995793f)
#define S_P1 ( 0.44721359549995793f)
#define S_P3 ( 1.3416407864998738f)
#define LOG2E 1.4426950408889634f
#define LN2   0.6931471805599453f

__device__ __forceinline__ float symval(int i) {
    float ab = (i & 1) ? S_M1 : S_M3;
    float cd = (i & 1) ? S_P3 : S_P1;
    return (i & 2) ? cd : ab;
}
// select one of 4 register values by 2-bit index (no local memory)
__device__ __forceinline__ float qsel(float a, float b, float c, float d, int i) {
    float ab = (i & 1) ? b : a;
    float cd = (i & 1) ? d : c;
    return (i & 2) ? cd : ab;
}
__device__ __forceinline__ float rowmax4(const float* v) {
    return fmaxf(fmaxf(v[0], v[1]), fmaxf(v[2], v[3]));
}
// Guaranteed single-MUFU ops regardless of fast-math flags
__device__ __forceinline__ float ex2a(float x) {
    float y; asm("ex2.approx.ftz.f32 %0, %1;" : "=f"(y) : "f"(x)); return y;
}
__device__ __forceinline__ float lg2a(float x) {
    float y; asm("lg2.approx.ftz.f32 %0, %1;" : "=f"(y) : "f"(x)); return y;
}
__device__ __forceinline__ float rcpa(float x) {
    float y; asm("rcp.approx.ftz.f32 %0, %1;" : "=f"(y) : "f"(x)); return y;
}
__device__ __forceinline__ float expn(float x) {   // e^x
    return ex2a(x * LOG2E);
}

__global__ __launch_bounds__(256, 3)
void mfnet_layer_kernel(const float* __restrict__ log_qi_in,
                        const float* __restrict__ G,
                        const float* __restrict__ sqrt_2rho,
                        const float* __restrict__ alpha_ptr,
                        float* __restrict__ out)
{
    const int gtid = blockIdx.x * blockDim.x + threadIdx.x;
    const int b    = gtid >> 5;          // one warp per batch item
    const int lane = gtid & 31;
    if (b >= NB) return;

    const float alpha = __ldg(alpha_ptr);
    const float rho2n = -__ldg(&sqrt_2rho[b]) * LOG2E;  // NEGATED, log2 units

    // k = i0*64 + i1*16 + i2*4 + i3 ; k = lane*8 + j
    // i0 = lane>>3, i1 = (lane>>1)&3, i2 = ((lane&1)<<1)|(j>>2), i3 = j&3
    const int i0 = lane >> 3;
    const int i1 = (lane >> 1) & 3;
    const int lb = lane & 1;

    const float s0    = qsel(S_M3, S_M1, S_P1, S_P3, i0);
    const float s1    = qsel(S_M3, S_M1, S_P1, S_P3, i1);
    const float si2_0 = lb ? S_P1 : S_M3;   // symval(2lb + 0)
    const float si2_1 = lb ? S_P3 : S_M1;   // symval(2lb + 1)

    // Negated per-r partials (log2 units): t2n[r][jc] = -rho2*(g0 s0 + g1 s1 + g2 si2_jc)
    // Positive row sums Tp[jc] = sum_r (-t2n), Cp = sum_r (-c3n) for the Sum(x) shortcut.
    float t2n[N_RX][2], c3n[N_RX];
    float Tp0 = 0.0f, Tp1 = 0.0f, Cp = 0.0f;
    const float4* Gv = reinterpret_cast<const float4*>(G) + (size_t)b * N_RX;
    #pragma unroll
    for (int r = 0; r < N_RX; r++) {
        float4 g    = Gv[r];
        float basen = rho2n * fmaf(g.x, s0, g.y * s1);
        float c2n   = rho2n * g.z;
        c3n[r]      = rho2n * g.w;
        t2n[r][0]   = fmaf(c2n, si2_0, basen);
        t2n[r][1]   = fmaf(c2n, si2_1, basen);
        Tp0 -= t2n[r][0];
        Tp1 -= t2n[r][1];
        Cp  -= c3n[r];
    }

    // log_p (log2 units) for this lane's 8 k-values.
    // logcdf2(x) = min(x,0) + log2(1 - 0.5*2^{-max(x,0)})
    //   Sum_r min(x,0) = Sum_r x + Sum_r min(-x,0);   Sum_r x = Tp[jc] + Cp*si3
    //   pn = min(-x, 0) = min(xn, 0);  e = 2^{pn};  h = 1 - 0.5 e in [0.5, 1) -> safe product, ONE lg2 per j
    float lp2[8];
    #pragma unroll
    for (int j = 0; j < 8; j++) {
        const int   jc  = j >> 2;
        const float si3 = symval(j & 3);
        float sum_pn = 0.0f, prod = 1.0f;
        #pragma unroll
        for (int r = 0; r < N_RX; r++) {
            float xn = fmaf(c3n[r], si3, t2n[r][jc]);   // -x
            float pn = fminf(xn, 0.0f);
            sum_pn += pn;
            float e = ex2a(pn);
            prod *= fmaf(-0.5f, e, 1.0f);
        }
        float sx = fmaf(Cp, si3, jc ? Tp1 : Tp0);       // Sum_r x
        lp2[j] = sx + sum_pn + lg2a(prod);
    }

    // Load log_qi [4][4]; stored values never shifted, per-row offset tracked lazily.
    float lq[4][4], off[4];
    const float4* Lv = reinterpret_cast<const float4*>(log_qi_in) + (size_t)b * 4;
    #pragma unroll
    for (int t = 0; t < 4; t++) {
        float4 v = Lv[t];
        lq[t][0] = v.x; lq[t][1] = v.y; lq[t][2] = v.z; lq[t][3] = v.w;
    }
    off[0] = 0.0f;                // row 0's first update uses the raw row (reference order)
    off[1] = rowmax4(lq[1]);
    off[2] = rowmax4(lq[2]);
    off[3] = rowmax4(lq[3]);

    // Initial softmax pieces (softmax is shift-invariant)
    float f0, f1, f2_0, f2_1, qi3[4];
    {
        float e0 = expn(lq[0][0]), e1 = expn(lq[0][1]), e2 = expn(lq[0][2]), e3 = expn(lq[0][3]);
        f0 = qsel(e0, e1, e2, e3, i0) * rcpa((e0 + e1) + (e2 + e3));
    }
    {
        float e0 = expn(lq[1][0]), e1 = expn(lq[1][1]), e2 = expn(lq[1][2]), e3 = expn(lq[1][3]);
        f1 = qsel(e0, e1, e2, e3, i1) * rcpa((e0 + e1) + (e2 + e3));
    }
    {
        float e0 = expn(lq[2][0]), e1 = expn(lq[2][1]), e2 = expn(lq[2][2]), e3 = expn(lq[2][3]);
        float inv = rcpa((e0 + e1) + (e2 + e3));
        f2_0 = (lb ? e2 : e0) * inv;
        f2_1 = (lb ? e3 : e1) * inv;
    }
    {
        float e0 = expn(lq[3][0]), e1 = expn(lq[3][1]), e2 = expn(lq[3][2]), e3 = expn(lq[3][3]);
        float inv = rcpa((e0 + e1) + (e2 + e3));
        qi3[0] = e0 * inv; qi3[1] = e1 * inv; qi3[2] = e2 * inv; qi3[3] = e3 * inv;
    }

    // Shared partials: ul0/ul1 valid through xi=0,1,2 (rows 2,3 unchanged until then)
    float ul0 = fmaf(qi3[3], lp2[3], fmaf(qi3[2], lp2[2], fmaf(qi3[1], lp2[1], qi3[0] * lp2[0])));
    float ul1 = fmaf(qi3[3], lp2[7], fmaf(qi3[2], lp2[6], fmaf(qi3[1], lp2[5], qi3[0] * lp2[4])));
    float sum_wl = fmaf(f2_1, ul1, f2_0 * ul0);

    const float ap  = alpha * LN2;     // acc is in log2 units -> fold ln2 into alpha
    const float oma = 1.0f - alpha;
    const unsigned FULL = 0xffffffffu;

    // ---- xi = 0 : bucket s = i0 (lane bits 3,4). Reduce over bits 0,1,2. ----
    {
        float a = f1 * sum_wl;
        a += __shfl_xor_sync(FULL, a, 1);
        a += __shfl_xor_sync(FULL, a, 2);
        a += __shfl_xor_sync(FULL, a, 4);
        float a0 = __shfl_sync(FULL, a, 0);
        float a1 = __shfl_sync(FULL, a, 8);
        float a2 = __shfl_sync(FULL, a, 16);
        float a3 = __shfl_sync(FULL, a, 24);
        float o = off[0];
        lq[0][0] = fmaf(oma, lq[0][0] - o, ap * a0);
        lq[0][1] = fmaf(oma, lq[0][1] - o, ap * a1);
        lq[0][2] = fmaf(oma, lq[0][2] - o, ap * a2);
        lq[0][3] = fmaf(oma, lq[0][3] - o, ap * a3);
        off[0] = rowmax4(lq[0]);
        float e0 = expn(lq[0][0] - off[0]), e1 = expn(lq[0][1] - off[0]);
        float e2 = expn(lq[0][2] - off[0]), e3 = expn(lq[0][3] - off[0]);
        f0 = qsel(e0, e1, e2, e3, i0) * rcpa((e0 + e1) + (e2 + e3));
    }

    // ---- xi = 1 : bucket s = i1 (lane bits 1,2). Reduce over bits 0,3,4. ----
    {
        float a = f0 * sum_wl;
        a += __shfl_xor_sync(FULL, a, 1);
        a += __shfl_xor_sync(FULL, a, 8);
        a += __shfl_xor_sync(FULL, a, 16);
        float a0 = __shfl_sync(FULL, a, 0);
        float a1 = __shfl_sync(FULL, a, 2);
        float a2 = __shfl_sync(FULL, a, 4);
        float a3 = __shfl_sync(FULL, a, 6);
        float o = off[1];
        lq[1][0] = fmaf(oma, lq[1][0] - o, ap * a0);
        lq[1][1] = fmaf(oma, lq[1][1] - o, ap * a1);
        lq[1][2] = fmaf(oma, lq[1][2] - o, ap * a2);
        lq[1][3] = fmaf(oma, lq[1][3] - o, ap * a3);
        off[1] = rowmax4(lq[1]);
        float e0 = expn(lq[1][0] - off[1]), e1 = expn(lq[1][1] - off[1]);
        float e2 = expn(lq[1][2] - off[1]), e3 = expn(lq[1][3] - off[1]);
        f1 = qsel(e0, e1, e2, e3, i1) * rcpa((e0 + e1) + (e2 + e3));
    }

    // ---- xi = 2 : bucket s = 2*lb + jc. Two accs per lane; reduce over bits 1..4. ----
    float g0, g1;   // f01 * new qi2 selects, for xi=3
    {
        float f01 = f0 * f1;
        float a0 = f01 * ul0;   // jc=0 -> bucket 2*lb
        float a1 = f01 * ul1;   // jc=1 -> bucket 2*lb+1
        a0 += __shfl_xor_sync(FULL, a0, 2);  a1 += __shfl_xor_sync(FULL, a1, 2);
        a0 += __shfl_xor_sync(FULL, a0, 4);  a1 += __shfl_xor_sync(FULL, a1, 4);
        a0 += __shfl_xor_sync(FULL, a0, 8);  a1 += __shfl_xor_sync(FULL, a1, 8);
        a0 += __shfl_xor_sync(FULL, a0, 16); a1 += __shfl_xor_sync(FULL, a1, 16);
        float b0 = __shfl_sync(FULL, a0, 0);
        float b1 = __shfl_sync(FULL, a1, 0);
        float b2 = __shfl_sync(FULL, a0, 1);
        float b3 = __shfl_sync(FULL, a1, 1);
        float o = off[2];
        lq[2][0] = fmaf(oma, lq[2][0] - o, ap * b0);
        lq[2][1] = fmaf(oma, lq[2][1] - o, ap * b1);
        lq[2][2] = fmaf(oma, lq[2][2] - o, ap * b2);
        lq[2][3] = fmaf(oma, lq[2][3] - o, ap * b3);
        off[2] = rowmax4(lq[2]);
        float e0 = expn(lq[2][0] - off[2]), e1 = expn(lq[2][1] - off[2]);
        float e2 = expn(lq[2][2] - off[2]), e3 = expn(lq[2][3] - off[2]);
        float inv = rcpa((e0 + e1) + (e2 + e3));
        g0 = f01 * ((lb ? e2 : e0) * inv);
        g1 = f01 * ((lb ? e3 : e1) * inv);
    }

    // ---- xi = 3 : bucket s = j&3. Per-lane 4 values; full butterfly. ----
    {
        float v0 = fmaf(g1, lp2[4], g0 * lp2[0]);
        float v1 = fmaf(g1, lp2[5], g0 * lp2[1]);
        float v2 = fmaf(g1, lp2[6], g0 * lp2[2]);
        float v3 = fmaf(g1, lp2[7], g0 * lp2[3]);
        #pragma unroll
        for (int st = 1; st <= 16; st <<= 1) {
            v0 += __shfl_xor_sync(FULL, v0, st);
            v1 += __shfl_xor_sync(FULL, v1, st);
            v2 += __shfl_xor_sync(FULL, v2, st);
            v3 += __shfl_xor_sync(FULL, v3, st);
        }
        float o = off[3];
        lq[3][0] = fmaf(oma, lq[3][0] - o, ap * v0);
        lq[3][1] = fmaf(oma, lq[3][1] - o, ap * v1);
        lq[3][2] = fmaf(oma, lq[3][2] - o, ap * v2);
        lq[3][3] = fmaf(oma, lq[3][3] - o, ap * v3);
        off[3] = rowmax4(lq[3]);
    }

    // Output: actual values = stored - off. Lanes 0..3 write rows 0..3 as float4.
    float r0 = qsel(lq[0][0] - off[0], lq[1][0] - off[1], lq[2][0] - off[2], lq[3][0] - off[3], lane);
    float r1 = qsel(lq[0][1] - off[0], lq[1][1] - off[1], lq[2][1] - off[2], lq[3][1] - off[3], lane);
    float r2 = qsel(lq[0][2] - off[0], lq[1][2] - off[1], lq[2][2] - off[2], lq[3][2] - off[3], lane);
    float r3 = qsel(lq[0][3] - off[0], lq[1][3] - off[1], lq[2][3] - off[2], lq[3][3] - off[3], lane);
    if (lane < 4) {
        reinterpret_cast<float4*>(out)[(size_t)b * 4 + lane] = make_float4(r0, r1, r2, r3);
    }
}

extern "C" void kernel_launch(void* const* d_in, const int* in_sizes, int n_in,
                              void* d_out, int out_size)
{
    const float* log_qi    = (const float*)d_in[0]; // (N,4,4)
    const float* G         = (const float*)d_in[1]; // (N,8,4)
    const float* sqrt_2rho = (const float*)d_in[2]; // (N,)
    // d_in[3] = n_var, unused by reference
    const float* alpha     = (const float*)d_in[4]; // scalar

    float* out = (float*)d_out;

    const int threads = 256;                 // 8 warps/block
    const int blocks  = (NB * 32) / threads; // 4096
    mfnet_layer_kernel<<<blocks, threads>>>(log_qi, G, sqrt_2rho, alpha, out);
}